// round 1
// baseline (speedup 1.0000x reference)
#include <cuda_runtime.h>
#include <cuda_bf16.h>

// Problem constants (fixed by the reference setup)
#define BATCH   2
#define NPTS    6144
#define DIM     32
#define RADIUS2 0.0009f      // 0.03^2
#define SIM_T   0.7f
#define EPS_N   1e-8f

#define FULLMASK 0xffffffffu

// Scratch (__device__ globals: no allocation allowed)
__device__ float4 g_q[BATCH * NPTS];      // (x, y, z, |p|^2), masked to 1e9 for non-leaf
__device__ float  g_norm[BATCH * NPTS];   // max(||emb||, eps)
__device__ int    g_leaf_idx[BATCH * NPTS];
__device__ int    g_leaf_cnt[BATCH];

// ---------------------------------------------------------------------------
// Kernel 0: zero the per-batch counters (graph replays must re-zero)
// ---------------------------------------------------------------------------
__global__ void zero_kernel() {
    if (threadIdx.x < BATCH) g_leaf_cnt[threadIdx.x] = 0;
}

// ---------------------------------------------------------------------------
// Kernel 1: prep. One warp per point.
//  - out = embeddings (default for all non-refined points / failed batches)
//  - g_norm = max(||emb||, 1e-8)
//  - g_q = (x,y,z,pn) if leaf else (1e9,1e9,1e9,3e18)  (folds leaf[j] into d2 test)
//  - compact leaf indices per batch (counter == sum(leaf_mask) since mask in {0,1})
// ---------------------------------------------------------------------------
__global__ __launch_bounds__(256) void prep_kernel(
    const float* __restrict__ points,
    const float* __restrict__ emb,
    const int*   __restrict__ leaf_mask,
    float*       __restrict__ out)
{
    int warp = (blockIdx.x * blockDim.x + threadIdx.x) >> 5;
    int lane = threadIdx.x & 31;
    if (warp >= BATCH * NPTS) return;
    int idx = warp;                 // global point index in [0, BATCH*NPTS)
    int b   = idx / NPTS;

    float e = emb[idx * DIM + lane];
    out[idx * DIM + lane] = e;      // default output

    float s = __fmul_rn(e, e);
    #pragma unroll
    for (int o = 16; o; o >>= 1) s += __shfl_xor_sync(FULLMASK, s, o);

    if (lane == 0) {
        g_norm[idx] = fmaxf(sqrtf(s), EPS_N);
        int lm = leaf_mask[idx];
        float x = points[idx * 3 + 0];
        float y = points[idx * 3 + 1];
        float z = points[idx * 3 + 2];
        float4 q;
        if (lm > 0) {
            // pn = (x*x + y*y) + z*z, explicit rn (match reference elementwise mul+sum)
            float pn = __fadd_rn(__fadd_rn(__fmul_rn(x, x), __fmul_rn(y, y)),
                                 __fmul_rn(z, z));
            q = make_float4(x, y, z, pn);
            int slot = atomicAdd(&g_leaf_cnt[b], 1);
            g_leaf_idx[b * NPTS + slot] = idx - b * NPTS;   // local index
        } else {
            q = make_float4(1e9f, 1e9f, 1e9f, 3e18f);       // forces d2 >> radius^2
        }
        g_q[idx] = q;
    }
}

// ---------------------------------------------------------------------------
// Kernel 2: main. One warp per LEAF point; all points of the batch staged in
// shared memory as float4. Gram-trick d2 (matches reference formulation).
// ---------------------------------------------------------------------------
#define MAIN_THREADS 512
#define WARPS_PER_BLOCK (MAIN_THREADS / 32)

__global__ __launch_bounds__(MAIN_THREADS) void main_kernel(
    const float* __restrict__ emb,
    const float* __restrict__ W1,
    const float* __restrict__ b1,
    const float* __restrict__ W2,
    const float* __restrict__ b2,
    float*       __restrict__ out)
{
    int b   = blockIdx.y;
    int cnt = g_leaf_cnt[b];
    if (cnt < 10) return;                           // batch early-exit: out stays = emb
    int warp0 = blockIdx.x * WARPS_PER_BLOCK;
    if (warp0 >= cnt) return;                       // fully-empty block: skip smem load

    extern __shared__ float4 sq[];                  // NPTS float4 = 96 KB
    const float4* qb = g_q + b * NPTS;
    for (int t = threadIdx.x; t < NPTS; t += MAIN_THREADS) sq[t] = qb[t];
    __syncthreads();

    int w    = warp0 + (threadIdx.x >> 5);
    int lane = threadIdx.x & 31;
    if (w >= cnt) return;

    int i  = g_leaf_idx[b * NPTS + w];
    int gi = b * NPTS + i;

    float4 qi = sq[i];
    float  ni = g_norm[gi];
    float  ei = emb[gi * DIM + lane];               // this lane's dim of emb_i

    const float* embb  = emb    + b * NPTS * DIM;
    const float* normb = g_norm + b * NPTS;

    float acc     = 0.0f;
    int   cnt_sim = 0;
    int   cnt_nb  = 0;

    #pragma unroll 4
    for (int jb = 0; jb < NPTS; jb += 32) {
        float4 qj = sq[jb + lane];
        // gram = xi*xj + yi*yj + zi*zj (fma chain, like a dot product)
        float g  = __fmaf_rn(qi.z, qj.z,
                   __fmaf_rn(qi.y, qj.y,
                   __fmul_rn(qi.x, qj.x)));
        // d2 = (pn_i + pn_j) - 2*gram   (clamp unnecessary: test is "< 9e-4")
        float d2 = __fadd_rn(__fadd_rn(qi.w, qj.w), __fmul_rn(-2.0f, g));
        unsigned m = __ballot_sync(FULLMASK, d2 < RADIUS2);
        cnt_nb += __popc(m);
        while (m) {
            int l = __ffs(m) - 1;
            m &= m - 1;
            int j = jb + l;
            float v = embb[j * DIM + lane];
            float p = __fmul_rn(v, ei);
            #pragma unroll
            for (int o = 16; o; o >>= 1) p += __shfl_xor_sync(FULLMASK, p, o);
            float sim = __fdiv_rn(p, __fmul_rn(ni, normb[j]));
            if (sim > SIM_T) { acc += v; cnt_sim++; }
        }
    }

    float mean = acc / (float)max(cnt_sim, 1);

    // MLP: h = relu([emb_i, mean] @ W1 + b1); o = h @ W2 + b2. Done via shuffles.
    float h = b1[lane];
    #pragma unroll
    for (int k = 0; k < 32; k++) {
        float ck = __shfl_sync(FULLMASK, ei, k);
        h = __fmaf_rn(ck, W1[k * DIM + lane], h);
    }
    #pragma unroll
    for (int k = 0; k < 32; k++) {
        float ck = __shfl_sync(FULLMASK, mean, k);
        h = __fmaf_rn(ck, W1[(k + 32) * DIM + lane], h);
    }
    h = fmaxf(h, 0.0f);

    float o = b2[lane];
    #pragma unroll
    for (int k = 0; k < 32; k++) {
        float hk = __shfl_sync(FULLMASK, h, k);
        o = __fmaf_rn(hk, W2[k * DIM + lane], o);
    }

    if (cnt_nb > 1 && cnt_sim > 0)
        out[gi * DIM + lane] = o;
}

// ---------------------------------------------------------------------------
extern "C" void kernel_launch(void* const* d_in, const int* in_sizes, int n_in,
                              void* d_out, int out_size)
{
    const float* points    = (const float*)d_in[0];
    const float* emb       = (const float*)d_in[1];
    const int*   leaf_mask = (const int*)  d_in[2];
    const float* W1        = (const float*)d_in[3];
    const float* b1        = (const float*)d_in[4];
    const float* W2        = (const float*)d_in[5];
    const float* b2        = (const float*)d_in[6];
    float* out = (float*)d_out;

    static_assert(sizeof(float4) == 16, "");
    size_t smem = NPTS * sizeof(float4);   // 98304 bytes
    cudaFuncSetAttribute(main_kernel, cudaFuncAttributeMaxDynamicSharedMemorySize,
                         (int)smem);

    zero_kernel<<<1, 32>>>();

    int total_warps = BATCH * NPTS;
    int prep_blocks = (total_warps * 32 + 255) / 256;
    prep_kernel<<<prep_blocks, 256>>>(points, emb, leaf_mask, out);

    dim3 grid((NPTS + WARPS_PER_BLOCK - 1) / WARPS_PER_BLOCK, BATCH);
    main_kernel<<<grid, MAIN_THREADS, smem>>>(emb, W1, b1, W2, b2, out);
}

// round 2
// speedup vs baseline: 1.0503x; 1.0503x over previous
#include <cuda_runtime.h>
#include <cuda_bf16.h>

// Problem constants (fixed by the reference setup)
#define BATCH   2
#define NPTS    6144
#define DIM     32
#define RADIUS2 0.0009f      // 0.03^2
#define SIM_T   0.7f
#define EPS_N   1e-8f

#define FULLMASK 0xffffffffu

#define SQ_SLOTS 3584        // compacted-leaf smem tile (cnt ~ Binom(6144,.5) ≈ 3072; 3584 > +13σ)
#define HL_CAP   128         // per-warp hit list capacity (expected hits ~13)
#define MAIN_THREADS 512
#define WPB (MAIN_THREADS / 32)

// Scratch (__device__ globals: no allocation allowed)
__device__ float4 g_q[BATCH * NPTS];      // (x, y, z, |p|^2) for every point
__device__ float  g_norm[BATCH * NPTS];   // max(||emb||, eps)
__device__ int    g_leaf_idx[BATCH * NPTS];
__device__ int    g_leaf_cnt[BATCH];

// ---------------------------------------------------------------------------
// Kernel 1: prep. One warp per point.
//  - out = embeddings (default for every non-refined point / failed batch)
//  - g_norm = max(||emb||, 1e-8)
//  - g_q = (x,y,z,pn) with pn matching the reference's elementwise mul+sum
// ---------------------------------------------------------------------------
__global__ __launch_bounds__(256) void prep_kernel(
    const float* __restrict__ points,
    const float* __restrict__ emb,
    float*       __restrict__ out)
{
    int warp = (blockIdx.x * blockDim.x + threadIdx.x) >> 5;
    int lane = threadIdx.x & 31;
    if (warp >= BATCH * NPTS) return;
    int idx = warp;

    float e = emb[idx * DIM + lane];
    out[idx * DIM + lane] = e;      // default output

    float s = __fmul_rn(e, e);
    #pragma unroll
    for (int o = 16; o; o >>= 1) s += __shfl_xor_sync(FULLMASK, s, o);

    if (lane == 0) {
        g_norm[idx] = fmaxf(sqrtf(s), EPS_N);
        float x = points[idx * 3 + 0];
        float y = points[idx * 3 + 1];
        float z = points[idx * 3 + 2];
        float pn = __fadd_rn(__fadd_rn(__fmul_rn(x, x), __fmul_rn(y, y)),
                             __fmul_rn(z, z));
        g_q[idx] = make_float4(x, y, z, pn);
    }
}

// ---------------------------------------------------------------------------
// Kernel 2: deterministic leaf compaction. One block per batch.
// Each thread owns a contiguous range of 24 points; block-wide Hillis-Steele
// scan gives each thread its write offset. Output order = ascending index
// (deterministic, replay-stable).
// ---------------------------------------------------------------------------
__global__ __launch_bounds__(256) void compact_kernel(
    const int* __restrict__ leaf_mask)
{
    int b = blockIdx.x;
    const int* m = leaf_mask + b * NPTS;
    __shared__ int sc[256];
    int t = threadIdx.x;
    const int PER = NPTS / 256;          // 24
    int base = t * PER;

    int c = 0;
    #pragma unroll
    for (int k = 0; k < PER; k++) c += (m[base + k] > 0);
    sc[t] = c;
    __syncthreads();

    // inclusive Hillis-Steele scan
    for (int d = 1; d < 256; d <<= 1) {
        int v = (t >= d) ? sc[t - d] : 0;
        __syncthreads();
        sc[t] += v;
        __syncthreads();
    }

    int off = sc[t] - c;                 // exclusive prefix
    int* dst = g_leaf_idx + b * NPTS;
    #pragma unroll
    for (int k = 0; k < PER; k++)
        if (m[base + k] > 0) dst[off++] = base + k;

    if (t == 255) g_leaf_cnt[b] = sc[255];
}

// ---------------------------------------------------------------------------
// Kernel 3: main. One warp per LEAF point. Compacted leaf q-tile + slot->idx
// map staged in smem. Phase A: distance scan over cnt leaf slots, appending
// hit indices to a per-warp smem list. Phase B: 4-way interleaved warp
// reductions over the hit list. Then the 64->32->32 MLP via shuffles.
// ---------------------------------------------------------------------------
__global__ __launch_bounds__(MAIN_THREADS, 3) void main_kernel(
    const float* __restrict__ emb,
    const float* __restrict__ W1,
    const float* __restrict__ b1,
    const float* __restrict__ W2,
    const float* __restrict__ b2,
    float*       __restrict__ out)
{
    int b   = blockIdx.y;
    int cnt = g_leaf_cnt[b];
    if (cnt < 10) return;                           // batch early-exit
    int warp0 = blockIdx.x * WPB;
    if (warp0 >= cnt) return;                       // empty block: skip staging

    extern __shared__ unsigned char smem_raw[];
    float4*         sq   = (float4*)smem_raw;                    // SQ_SLOTS
    unsigned short* sidx = (unsigned short*)(sq + SQ_SLOTS);     // SQ_SLOTS
    unsigned short* hl   = sidx + SQ_SLOTS;                      // WPB*HL_CAP

    const float4* qb   = g_q        + b * NPTS;
    const int*    lidx = g_leaf_idx + b * NPTS;

    int lim = min(cnt, SQ_SLOTS);
    for (int t = threadIdx.x; t < lim; t += MAIN_THREADS) {
        int idx = lidx[t];
        sidx[t] = (unsigned short)idx;
        sq[t]   = qb[idx];
    }
    __syncthreads();

    int wid  = threadIdx.x >> 5;
    int lane = threadIdx.x & 31;
    int w    = warp0 + wid;
    if (w >= cnt) return;

    int i  = lidx[w];
    int gi = b * NPTS + i;

    float4 qi = (w < SQ_SLOTS) ? sq[w] : qb[i];
    float  ni = g_norm[gi];
    float  ei = emb[gi * DIM + lane];               // this lane's dim of emb_i

    const float* embb  = emb    + b * NPTS * DIM;
    const float* normb = g_norm + b * NPTS;
    unsigned short* myhl = hl + wid * HL_CAP;

    float acc     = 0.0f;
    int   cnt_sim = 0;
    int   cnt_nb  = 0;
    int   nhit    = 0;

    // ---- Phase A: distance scan over compacted leaf slots ----
    for (int jb = 0; jb < cnt; jb += 32) {
        int s = jb + lane;
        float4 qj;
        int jg = 0;
        bool inb = (s < cnt);
        if (inb) {
            if (s < SQ_SLOTS) { qj = sq[s]; jg = sidx[s]; }
            else              { jg = lidx[s]; qj = qb[jg]; }   // cold fallback
        } else {
            qj.x = 1e9f; qj.y = 1e9f; qj.z = 1e9f; qj.w = 3e18f;
        }
        // gram = dot(pi,pj), d2 = pn_i + pn_j - 2*gram  (matches reference)
        float g  = __fmaf_rn(qi.z, qj.z,
                   __fmaf_rn(qi.y, qj.y,
                   __fmul_rn(qi.x, qj.x)));
        float d2 = __fadd_rn(__fadd_rn(qi.w, qj.w), __fmul_rn(-2.0f, g));
        bool hit = inb && (d2 < RADIUS2);
        unsigned m = __ballot_sync(FULLMASK, hit);
        int nh = __popc(m);
        cnt_nb += nh;
        if (nhit + nh <= HL_CAP) {
            if (hit)
                myhl[nhit + __popc(m & ((1u << lane) - 1u))] = (unsigned short)jg;
            nhit += nh;
        } else {
            // hit-list overflow: process this chunk inline (essentially never)
            while (m) {
                int l = __ffs(m) - 1; m &= m - 1;
                int j = __shfl_sync(FULLMASK, jg, l);
                float v = embb[j * DIM + lane];
                float p = __fmul_rn(v, ei);
                #pragma unroll
                for (int o = 16; o; o >>= 1) p += __shfl_xor_sync(FULLMASK, p, o);
                float sim = __fdiv_rn(p, __fmul_rn(ni, normb[j]));
                if (sim > SIM_T) { acc += v; cnt_sim++; }
            }
        }
    }

    // ---- Phase B: 4-way interleaved similarity reductions over the hit list ----
    for (int t = 0; t < nhit; t += 4) {
        int r = nhit - t;
        int j0 = myhl[t];
        int j1 = myhl[t + ((r > 1) ? 1 : 0)];
        int j2 = myhl[t + ((r > 2) ? 2 : 0)];
        int j3 = myhl[t + ((r > 3) ? 3 : 0)];

        float v0 = embb[j0 * DIM + lane];
        float v1 = embb[j1 * DIM + lane];
        float v2 = embb[j2 * DIM + lane];
        float v3 = embb[j3 * DIM + lane];
        float n0 = normb[j0], n1 = normb[j1], n2 = normb[j2], n3 = normb[j3];

        float p0 = __fmul_rn(v0, ei);
        float p1 = __fmul_rn(v1, ei);
        float p2 = __fmul_rn(v2, ei);
        float p3 = __fmul_rn(v3, ei);
        #pragma unroll
        for (int o = 16; o; o >>= 1) {
            p0 += __shfl_xor_sync(FULLMASK, p0, o);
            p1 += __shfl_xor_sync(FULLMASK, p1, o);
            p2 += __shfl_xor_sync(FULLMASK, p2, o);
            p3 += __shfl_xor_sync(FULLMASK, p3, o);
        }
        float s0 = __fdiv_rn(p0, __fmul_rn(ni, n0));
        float s1 = __fdiv_rn(p1, __fmul_rn(ni, n1));
        float s2 = __fdiv_rn(p2, __fmul_rn(ni, n2));
        float s3 = __fdiv_rn(p3, __fmul_rn(ni, n3));

        if (s0 > SIM_T)          { acc += v0; cnt_sim++; }
        if (r > 1 && s1 > SIM_T) { acc += v1; cnt_sim++; }
        if (r > 2 && s2 > SIM_T) { acc += v2; cnt_sim++; }
        if (r > 3 && s3 > SIM_T) { acc += v3; cnt_sim++; }
    }

    float mean = acc / (float)max(cnt_sim, 1);

    // ---- MLP: h = relu([emb_i, mean] @ W1 + b1); o = h @ W2 + b2 ----
    float h = b1[lane];
    #pragma unroll
    for (int k = 0; k < 32; k++) {
        float ck = __shfl_sync(FULLMASK, ei, k);
        h = __fmaf_rn(ck, W1[k * DIM + lane], h);
    }
    #pragma unroll
    for (int k = 0; k < 32; k++) {
        float ck = __shfl_sync(FULLMASK, mean, k);
        h = __fmaf_rn(ck, W1[(k + 32) * DIM + lane], h);
    }
    h = fmaxf(h, 0.0f);

    float o = b2[lane];
    #pragma unroll
    for (int k = 0; k < 32; k++) {
        float hk = __shfl_sync(FULLMASK, h, k);
        o = __fmaf_rn(hk, W2[k * DIM + lane], o);
    }

    if (cnt_nb > 1 && cnt_sim > 0)
        out[gi * DIM + lane] = o;
}

// ---------------------------------------------------------------------------
extern "C" void kernel_launch(void* const* d_in, const int* in_sizes, int n_in,
                              void* d_out, int out_size)
{
    const float* points    = (const float*)d_in[0];
    const float* emb       = (const float*)d_in[1];
    const int*   leaf_mask = (const int*)  d_in[2];
    const float* W1        = (const float*)d_in[3];
    const float* b1        = (const float*)d_in[4];
    const float* W2        = (const float*)d_in[5];
    const float* b2        = (const float*)d_in[6];
    float* out = (float*)d_out;

    size_t smem = SQ_SLOTS * sizeof(float4)
                + SQ_SLOTS * sizeof(unsigned short)
                + WPB * HL_CAP * sizeof(unsigned short);   // 66560 B
    cudaFuncSetAttribute(main_kernel, cudaFuncAttributeMaxDynamicSharedMemorySize,
                         (int)smem);

    int total_warps = BATCH * NPTS;
    int prep_blocks = (total_warps * 32 + 255) / 256;
    prep_kernel<<<prep_blocks, 256>>>(points, emb, out);

    compact_kernel<<<BATCH, 256>>>(leaf_mask);

    dim3 grid((NPTS + WPB - 1) / WPB, BATCH);
    main_kernel<<<grid, MAIN_THREADS, smem>>>(emb, W1, b1, W2, b2, out);
}

// round 4
// speedup vs baseline: 1.7729x; 1.6880x over previous
#include <cuda_runtime.h>
#include <cuda_bf16.h>

#define BATCH   2
#define NPTS    6144
#define DIM     32
#define RADIUS2 0.0009f      // 0.03^2
#define SIM_T   0.7f
#define EPS_N   1e-8f
#define FULLMASK 0xffffffffu

#define GRID1   10           // cells per axis
#define NCELLS  1000
#define INV_CELL 33.0f       // cell width = 1/33 = 0.0303 > radius (robust margin)

#define HL_CAP  96           // per-warp hit list (expected hits ~13)
#define MT      256          // main kernel threads
#define MWPB    (MT / 32)

// -------- scratch (__device__ globals; no allocation allowed) --------
__device__ float4 g_q[BATCH * NPTS];          // (x,y,z,|p|^2) per original point
__device__ float  g_norm[BATCH * NPTS];       // max(||emb||, eps)
__device__ int    g_cell[BATCH * NPTS];       // cell id if leaf, -1 if not
__device__ float4 g_bq[BATCH * NPTS];         // binned leaf points (cell-sorted)
__device__ unsigned short g_bidx[BATCH * NPTS]; // binned -> original local index
__device__ int    g_cellstart[BATCH * (NCELLS + 1)];
__device__ int    g_leaf_cnt[BATCH];

__device__ __forceinline__ int cell_of(float x, float y, float z) {
    int cx = (int)floorf(x * INV_CELL);
    int cy = (int)floorf(y * INV_CELL);
    int cz = (int)floorf(z * INV_CELL);
    cx = min(max(cx, 0), GRID1 - 1);
    cy = min(max(cy, 0), GRID1 - 1);
    cz = min(max(cz, 0), GRID1 - 1);
    return (cx * GRID1 + cy) * GRID1 + cz;
}

// ---------------------------------------------------------------------------
// Kernel 1: prep. 8 threads per point.
//   out = emb (float4 copy), g_norm, g_q = (x,y,z,pn), g_cell = leaf? cell : -1
// ---------------------------------------------------------------------------
__global__ __launch_bounds__(256) void prep_kernel(
    const float* __restrict__ points,
    const float* __restrict__ emb,
    const int*   __restrict__ leaf_mask,
    float*       __restrict__ out)
{
    int tid = blockIdx.x * blockDim.x + threadIdx.x;
    int p    = tid >> 3;           // point id
    int part = tid & 7;            // float4 index within the 32-dim row
    if (p >= BATCH * NPTS) return;

    const float4* e4 = (const float4*)emb;
    float4 v = e4[p * 8 + part];
    ((float4*)out)[p * 8 + part] = v;

    float s = __fmaf_rn(v.w, v.w,
              __fmaf_rn(v.z, v.z,
              __fmaf_rn(v.y, v.y, __fmul_rn(v.x, v.x))));
    #pragma unroll
    for (int o = 1; o < 8; o <<= 1) s += __shfl_xor_sync(FULLMASK, s, o);

    if (part == 0) {
        g_norm[p] = fmaxf(sqrtf(s), EPS_N);
        float x = points[p * 3 + 0];
        float y = points[p * 3 + 1];
        float z = points[p * 3 + 2];
        float pn = __fadd_rn(__fadd_rn(__fmul_rn(x, x), __fmul_rn(y, y)),
                             __fmul_rn(z, z));
        g_q[p] = make_float4(x, y, z, pn);
        g_cell[p] = (leaf_mask[p] > 0) ? cell_of(x, y, z) : -1;
    }
}

// ---------------------------------------------------------------------------
// Kernel 2: bin leaf points by cell. One block (1024 thr) per batch.
// histogram (smem atomics, order-independent) -> scan -> scatter (atomic
// cursors; within-cell order nondeterministic, fixed later by hit-list sort).
// ---------------------------------------------------------------------------
__global__ __launch_bounds__(1024) void bin_kernel()
{
    int b = blockIdx.x;
    int t = threadIdx.x;
    __shared__ int hist[NCELLS];      // then reused as scatter cursors
    __shared__ int scanb[1024];
    __shared__ int cstart[NCELLS + 1];

    if (t < NCELLS) hist[t] = 0;
    __syncthreads();

    const int PER = NPTS / 1024;      // 6
    int base = b * NPTS + t * PER;
    int cc[PER];
    #pragma unroll
    for (int k = 0; k < PER; k++) {
        cc[k] = g_cell[base + k];
        if (cc[k] >= 0) atomicAdd(&hist[cc[k]], 1);
    }
    __syncthreads();

    // inclusive Hillis-Steele scan over NCELLS (padded to 1024)
    scanb[t] = (t < NCELLS) ? hist[t] : 0;
    __syncthreads();
    for (int d = 1; d < 1024; d <<= 1) {
        int v = (t >= d) ? scanb[t - d] : 0;
        __syncthreads();
        scanb[t] += v;
        __syncthreads();
    }
    if (t < NCELLS) cstart[t + 1] = scanb[t];
    if (t == 0) cstart[0] = 0;
    __syncthreads();

    if (t <= NCELLS) g_cellstart[b * (NCELLS + 1) + t] = cstart[t];
    if (t == 0) g_leaf_cnt[b] = cstart[NCELLS];
    if (t < NCELLS) hist[t] = cstart[t];   // cursors
    __syncthreads();

    #pragma unroll
    for (int k = 0; k < PER; k++) {
        if (cc[k] >= 0) {
            int slot = atomicAdd(&hist[cc[k]], 1);
            int p = base + k;
            g_bq[b * NPTS + slot]   = g_q[p];
            g_bidx[b * NPTS + slot] = (unsigned short)(p - b * NPTS);
        }
    }
}

// ---------------------------------------------------------------------------
// Kernel 3: main. One warp per binned leaf query. 27-cell neighborhood scan
// (9 contiguous z-row ranges), hit list -> sort by original index
// (determinism) -> 4-way interleaved similarity reductions -> MLP (smem W).
// ---------------------------------------------------------------------------
__global__ __launch_bounds__(MT) void main_kernel(
    const float* __restrict__ emb,
    const float* __restrict__ W1,
    const float* __restrict__ b1,
    const float* __restrict__ W2,
    const float* __restrict__ b2,
    float*       __restrict__ out)
{
    __shared__ float sW1[64 * 32];
    __shared__ float sW2[32 * 32];
    __shared__ float sb1[32], sb2[32];
    __shared__ unsigned short hl[MWPB * HL_CAP];

    int b   = blockIdx.y;
    int cnt = g_leaf_cnt[b];

    // stage MLP weights (even if this block early-exits, cheap)
    for (int k = threadIdx.x; k < 64 * 32; k += MT) sW1[k] = W1[k];
    for (int k = threadIdx.x; k < 32 * 32; k += MT) sW2[k] = W2[k];
    if (threadIdx.x < 32) { sb1[threadIdx.x] = b1[threadIdx.x];
                            sb2[threadIdx.x] = b2[threadIdx.x]; }
    __syncthreads();

    if (cnt < 10) return;                        // batch early-exit
    int wid  = threadIdx.x >> 5;
    int lane = threadIdx.x & 31;
    int w    = blockIdx.x * MWPB + wid;
    if (w >= cnt) return;

    int sb_ = b * NPTS;
    float4 qi = g_bq[sb_ + w];
    int    i  = g_bidx[sb_ + w];
    int    gi = sb_ + i;

    float ni = g_norm[gi];
    float ei = emb[gi * DIM + lane];

    const float* embb  = emb    + sb_ * DIM;
    const float* normb = g_norm + sb_;
    const int*   cs    = g_cellstart + b * (NCELLS + 1);
    unsigned short* myhl = hl + wid * HL_CAP;

    int cx = min(max((int)floorf(qi.x * INV_CELL), 0), GRID1 - 1);
    int cy = min(max((int)floorf(qi.y * INV_CELL), 0), GRID1 - 1);
    int cz = min(max((int)floorf(qi.z * INV_CELL), 0), GRID1 - 1);
    int zlo = max(cz - 1, 0), zhi = min(cz + 1, GRID1 - 1);

    float acc = 0.0f;
    int cnt_sim = 0, cnt_nb = 0, nhit = 0;

    // ---- Phase A: scan 9 (x,y) rows of the 3x3x3 neighborhood ----
    for (int dx = -1; dx <= 1; dx++) {
        int X = cx + dx;
        if ((unsigned)X >= GRID1) continue;
        for (int dy = -1; dy <= 1; dy++) {
            int Y = cy + dy;
            if ((unsigned)Y >= GRID1) continue;
            int row = (X * GRID1 + Y) * GRID1;
            int s0 = cs[row + zlo];
            int s1 = cs[row + zhi + 1];
            for (int sbase = s0; sbase < s1; sbase += 32) {
                int s = sbase + lane;
                bool act = (s < s1);
                float4 qj;
                if (act) qj = g_bq[sb_ + s];
                else { qj.x = 1e9f; qj.y = 1e9f; qj.z = 1e9f; qj.w = 3e18f; }
                float g  = __fmaf_rn(qi.z, qj.z,
                           __fmaf_rn(qi.y, qj.y,
                           __fmul_rn(qi.x, qj.x)));
                float d2 = __fadd_rn(__fadd_rn(qi.w, qj.w), __fmul_rn(-2.0f, g));
                bool hit = act && (d2 < RADIUS2);
                unsigned m = __ballot_sync(FULLMASK, hit);
                int nh = __popc(m);
                cnt_nb += nh;
                int jj = hit ? (int)g_bidx[sb_ + s] : 0;
                if (nhit + nh <= HL_CAP) {
                    if (hit)
                        myhl[nhit + __popc(m & ((1u << lane) - 1u))] =
                            (unsigned short)jj;
                    nhit += nh;
                } else {
                    // overflow: process inline (pathological inputs only)
                    while (m) {
                        int l = __ffs(m) - 1; m &= m - 1;
                        int j = __shfl_sync(FULLMASK, jj, l);
                        float v = embb[j * DIM + lane];
                        float p = __fmul_rn(v, ei);
                        #pragma unroll
                        for (int o = 16; o; o >>= 1)
                            p += __shfl_xor_sync(FULLMASK, p, o);
                        float sim = __fdiv_rn(p, __fmul_rn(ni, normb[j]));
                        if (sim > SIM_T) { acc += v; cnt_sim++; }
                    }
                }
            }
        }
    }

    // ---- sort hit list ascending by original index (deterministic order) ----
    if (nhit <= 32) {
        int v = (lane < nhit) ? (int)myhl[lane] : 0x10000;
        #pragma unroll
        for (int k = 2; k <= 32; k <<= 1) {
            #pragma unroll
            for (int j = k >> 1; j > 0; j >>= 1) {
                int o = __shfl_xor_sync(FULLMASK, v, j);
                bool up    = ((lane & k) == 0);
                bool lower = ((lane & j) == 0);
                v = (up == lower) ? min(v, o) : max(v, o);
            }
        }
        if (lane < nhit) myhl[lane] = (unsigned short)v;
    } else if (lane == 0) {                      // rare path
        for (int a = 1; a < nhit; a++) {
            unsigned short key = myhl[a];
            int c = a - 1;
            while (c >= 0 && myhl[c] > key) { myhl[c + 1] = myhl[c]; c--; }
            myhl[c + 1] = key;
        }
    }
    __syncwarp();

    // ---- Phase B: 4-way interleaved similarity reductions ----
    for (int t = 0; t < nhit; t += 4) {
        int r = nhit - t;
        int j0 = myhl[t];
        int j1 = myhl[t + ((r > 1) ? 1 : 0)];
        int j2 = myhl[t + ((r > 2) ? 2 : 0)];
        int j3 = myhl[t + ((r > 3) ? 3 : 0)];

        float v0 = embb[j0 * DIM + lane];
        float v1 = embb[j1 * DIM + lane];
        float v2 = embb[j2 * DIM + lane];
        float v3 = embb[j3 * DIM + lane];
        float n0 = normb[j0], n1 = normb[j1], n2 = normb[j2], n3 = normb[j3];

        float p0 = __fmul_rn(v0, ei);
        float p1 = __fmul_rn(v1, ei);
        float p2 = __fmul_rn(v2, ei);
        float p3 = __fmul_rn(v3, ei);
        #pragma unroll
        for (int o = 16; o; o >>= 1) {
            p0 += __shfl_xor_sync(FULLMASK, p0, o);
            p1 += __shfl_xor_sync(FULLMASK, p1, o);
            p2 += __shfl_xor_sync(FULLMASK, p2, o);
            p3 += __shfl_xor_sync(FULLMASK, p3, o);
        }
        float s0 = __fdiv_rn(p0, __fmul_rn(ni, n0));
        float s1 = __fdiv_rn(p1, __fmul_rn(ni, n1));
        float s2 = __fdiv_rn(p2, __fmul_rn(ni, n2));
        float s3 = __fdiv_rn(p3, __fmul_rn(ni, n3));

        if (s0 > SIM_T)          { acc += v0; cnt_sim++; }
        if (r > 1 && s1 > SIM_T) { acc += v1; cnt_sim++; }
        if (r > 2 && s2 > SIM_T) { acc += v2; cnt_sim++; }
        if (r > 3 && s3 > SIM_T) { acc += v3; cnt_sim++; }
    }

    float mean = acc / (float)max(cnt_sim, 1);

    // ---- MLP: h = relu([emb_i, mean] @ W1 + b1); o = h @ W2 + b2 ----
    float h = sb1[lane];
    #pragma unroll
    for (int k = 0; k < 32; k++) {
        float ck = __shfl_sync(FULLMASK, ei, k);
        h = __fmaf_rn(ck, sW1[k * DIM + lane], h);
    }
    #pragma unroll
    for (int k = 0; k < 32; k++) {
        float ck = __shfl_sync(FULLMASK, mean, k);
        h = __fmaf_rn(ck, sW1[(k + 32) * DIM + lane], h);
    }
    h = fmaxf(h, 0.0f);

    float o = sb2[lane];
    #pragma unroll
    for (int k = 0; k < 32; k++) {
        float hk = __shfl_sync(FULLMASK, h, k);
        o = __fmaf_rn(hk, sW2[k * DIM + lane], o);
    }

    if (cnt_nb > 1 && cnt_sim > 0)
        out[gi * DIM + lane] = o;
}

// ---------------------------------------------------------------------------
extern "C" void kernel_launch(void* const* d_in, const int* in_sizes, int n_in,
                              void* d_out, int out_size)
{
    const float* points    = (const float*)d_in[0];
    const float* emb       = (const float*)d_in[1];
    const int*   leaf_mask = (const int*)  d_in[2];
    const float* W1        = (const float*)d_in[3];
    const float* b1        = (const float*)d_in[4];
    const float* W2        = (const float*)d_in[5];
    const float* b2        = (const float*)d_in[6];
    float* out = (float*)d_out;

    int prep_threads = BATCH * NPTS * 8;
    prep_kernel<<<(prep_threads + 255) / 256, 256>>>(points, emb, leaf_mask, out);

    bin_kernel<<<BATCH, 1024>>>();

    dim3 grid((NPTS + MWPB - 1) / MWPB, BATCH);
    main_kernel<<<grid, MT>>>(emb, W1, b1, W2, b2, out);
}

// round 5
// speedup vs baseline: 2.0395x; 1.1504x over previous
#include <cuda_runtime.h>
#include <cuda_bf16.h>

#define BATCH   2
#define NPTS    6144
#define DIM     32
#define RADIUS2 0.0009f      // 0.03^2
#define SIM_T   0.7f
#define EPS_N   1e-8f
#define FULLMASK 0xffffffffu

#define GRID1   10           // cells per axis
#define NCELLS  1000
#define INV_CELL 33.0f       // cell width = 1/33 = 0.0303 > radius (robust margin)

#define HL_CAP  96           // per-warp hit list (expected hits ~13)
#define MT      512          // main kernel threads
#define MWPB    (MT / 32)    // 16 warps per block

// -------- scratch (__device__ globals; no allocation allowed) --------
__device__ float4 g_q[BATCH * NPTS];            // (x,y,z,|p|^2) per point
__device__ float  g_norm[BATCH * NPTS];         // max(||emb||, eps)
__device__ int    g_cell[BATCH * NPTS];         // cell id if leaf, -1 if not
__device__ int    g_hist[BATCH * NCELLS];       // zero-init; re-zeroed by main
__device__ int    g_cur[BATCH * NCELLS];        // scatter cursors (set by scan)
__device__ float4 g_bq[BATCH * NPTS];           // binned leaf points
__device__ unsigned short g_bidx[BATCH * NPTS]; // binned -> original local idx
__device__ int    g_cellstart[BATCH * (NCELLS + 1)];
__device__ int    g_leaf_cnt[BATCH];

__device__ __forceinline__ int cell_of(float x, float y, float z) {
    int cx = (int)floorf(x * INV_CELL);
    int cy = (int)floorf(y * INV_CELL);
    int cz = (int)floorf(z * INV_CELL);
    cx = min(max(cx, 0), GRID1 - 1);
    cy = min(max(cy, 0), GRID1 - 1);
    cz = min(max(cz, 0), GRID1 - 1);
    return (cx * GRID1 + cy) * GRID1 + cz;
}

// ---------------------------------------------------------------------------
// Kernel 1: prep (role-split).
//   copy role : 4 independent float4s per thread  (out = emb)
//   point role: 1 point per thread -> norm (8 indep loads), g_q, g_cell,
//               global histogram atomicAdd (replaces bin histogram)
// ---------------------------------------------------------------------------
#define NP        (BATCH * NPTS)                 // 12288 points
#define COPY_THR  (NP * 8 / 4)                   // 24576 copy threads (4 f4 each)
#define PREP_THR  (COPY_THR + NP)                // + 12288 point threads

__global__ __launch_bounds__(256) void prep_kernel(
    const float* __restrict__ points,
    const float* __restrict__ emb,
    const int*   __restrict__ leaf_mask,
    float*       __restrict__ out)
{
    int tid = blockIdx.x * blockDim.x + threadIdx.x;
    if (tid < COPY_THR) {
        // ---- copy role: out = emb, 64B per thread, 4 loads in flight ----
        const float4* src = (const float4*)emb;
        float4*       dst = (float4*)out;
        int base = tid * 4;
        float4 v0 = src[base + 0];
        float4 v1 = src[base + 1];
        float4 v2 = src[base + 2];
        float4 v3 = src[base + 3];
        dst[base + 0] = v0;
        dst[base + 1] = v1;
        dst[base + 2] = v2;
        dst[base + 3] = v3;
        return;
    }
    int p = tid - COPY_THR;                      // point id
    if (p >= NP) return;

    // ---- point role: norm (one full 128B row per thread, 8 indep loads) ----
    const float4* e4 = (const float4*)(emb) + p * 8;
    float s = 0.0f;
    #pragma unroll
    for (int k = 0; k < 8; k++) {
        float4 v = e4[k];
        s += __fmaf_rn(v.w, v.w,
             __fmaf_rn(v.z, v.z,
             __fmaf_rn(v.y, v.y, __fmul_rn(v.x, v.x))));
    }
    g_norm[p] = fmaxf(sqrtf(s), EPS_N);

    float x = points[p * 3 + 0];
    float y = points[p * 3 + 1];
    float z = points[p * 3 + 2];
    float pn = __fadd_rn(__fadd_rn(__fmul_rn(x, x), __fmul_rn(y, y)),
                         __fmul_rn(z, z));
    g_q[p] = make_float4(x, y, z, pn);

    int b = p / NPTS;
    if (leaf_mask[p] > 0) {
        int c = cell_of(x, y, z);
        g_cell[p] = c;
        atomicAdd(&g_hist[b * NCELLS + c], 1);
    } else {
        g_cell[p] = -1;
    }
}

// ---------------------------------------------------------------------------
// Kernel 2: scan histogram -> cellstart + cursors + leaf_cnt. One block/batch.
// ---------------------------------------------------------------------------
__global__ __launch_bounds__(1024) void scan_kernel()
{
    int b = blockIdx.x;
    int t = threadIdx.x;
    __shared__ int sc[1024];

    int h = (t < NCELLS) ? g_hist[b * NCELLS + t] : 0;
    sc[t] = h;
    __syncthreads();
    for (int d = 1; d < 1024; d <<= 1) {
        int v = (t >= d) ? sc[t - d] : 0;
        __syncthreads();
        sc[t] += v;
        __syncthreads();
    }
    if (t < NCELLS) {
        int start = sc[t] - h;                   // exclusive prefix
        g_cellstart[b * (NCELLS + 1) + t] = start;
        g_cur[b * NCELLS + t] = start;
    }
    if (t == NCELLS - 1) {
        g_cellstart[b * (NCELLS + 1) + NCELLS] = sc[t];
        g_leaf_cnt[b] = sc[t];
    }
}

// ---------------------------------------------------------------------------
// Kernel 3: parallel scatter. One thread per point.
// (Within-cell order nondeterministic; fixed by hit-list sort in main.)
// ---------------------------------------------------------------------------
__global__ __launch_bounds__(256) void scatter_kernel()
{
    int p = blockIdx.x * blockDim.x + threadIdx.x;
    if (p >= NP) return;
    int c = g_cell[p];
    if (c < 0) return;
    int b = p / NPTS;
    int slot = atomicAdd(&g_cur[b * NCELLS + c], 1);
    g_bq[b * NPTS + slot]   = g_q[p];
    g_bidx[b * NPTS + slot] = (unsigned short)(p - b * NPTS);
}

// ---------------------------------------------------------------------------
// Kernel 4: main. One warp per binned leaf query. Also re-zeroes g_hist for
// the next graph replay (block (0,0), before any early exit).
// ---------------------------------------------------------------------------
__global__ __launch_bounds__(MT) void main_kernel(
    const float* __restrict__ emb,
    const float* __restrict__ W1,
    const float* __restrict__ b1,
    const float* __restrict__ W2,
    const float* __restrict__ b2,
    float*       __restrict__ out)
{
    __shared__ float sW1[64 * 32];
    __shared__ float sW2[32 * 32];
    __shared__ float sb1[32], sb2[32];
    __shared__ unsigned short hl[MWPB * HL_CAP];

    // re-zero histogram for next replay (hist already consumed by scan)
    if (blockIdx.x == 0 && blockIdx.y == 0) {
        for (int k = threadIdx.x; k < BATCH * NCELLS; k += MT) g_hist[k] = 0;
    }

    int b   = blockIdx.y;
    int cnt = g_leaf_cnt[b];
    if (cnt < 10) return;                        // batch early-exit (uniform)
    int warp0 = blockIdx.x * MWPB;
    if (warp0 >= cnt) return;                    // dead block (uniform)

    // stage MLP weights (live blocks only)
    for (int k = threadIdx.x; k < 64 * 32; k += MT) sW1[k] = W1[k];
    for (int k = threadIdx.x; k < 32 * 32; k += MT) sW2[k] = W2[k];
    if (threadIdx.x < 32) { sb1[threadIdx.x] = b1[threadIdx.x];
                            sb2[threadIdx.x] = b2[threadIdx.x]; }
    __syncthreads();

    int wid  = threadIdx.x >> 5;
    int lane = threadIdx.x & 31;
    int w    = warp0 + wid;
    if (w >= cnt) return;

    int sb_ = b * NPTS;
    float4 qi = g_bq[sb_ + w];
    int    i  = g_bidx[sb_ + w];
    int    gi = sb_ + i;

    float ni = g_norm[gi];
    float ei = emb[gi * DIM + lane];

    const float* embb  = emb    + sb_ * DIM;
    const float* normb = g_norm + sb_;
    const int*   cs    = g_cellstart + b * (NCELLS + 1);
    unsigned short* myhl = hl + wid * HL_CAP;

    int cx = min(max((int)floorf(qi.x * INV_CELL), 0), GRID1 - 1);
    int cy = min(max((int)floorf(qi.y * INV_CELL), 0), GRID1 - 1);
    int cz = min(max((int)floorf(qi.z * INV_CELL), 0), GRID1 - 1);
    int zlo = max(cz - 1, 0), zhi = min(cz + 1, GRID1 - 1);

    float acc = 0.0f;
    int cnt_sim = 0, cnt_nb = 0, nhit = 0;

    // ---- Phase A: scan 9 (x,y) rows of the 3x3x3 neighborhood ----
    for (int dx = -1; dx <= 1; dx++) {
        int X = cx + dx;
        if ((unsigned)X >= GRID1) continue;
        for (int dy = -1; dy <= 1; dy++) {
            int Y = cy + dy;
            if ((unsigned)Y >= GRID1) continue;
            int row = (X * GRID1 + Y) * GRID1;
            int s0 = cs[row + zlo];
            int s1 = cs[row + zhi + 1];
            for (int sbase = s0; sbase < s1; sbase += 32) {
                int s = sbase + lane;
                bool act = (s < s1);
                float4 qj;
                if (act) qj = g_bq[sb_ + s];
                else { qj.x = 1e9f; qj.y = 1e9f; qj.z = 1e9f; qj.w = 3e18f; }
                float g  = __fmaf_rn(qi.z, qj.z,
                           __fmaf_rn(qi.y, qj.y,
                           __fmul_rn(qi.x, qj.x)));
                float d2 = __fadd_rn(__fadd_rn(qi.w, qj.w), __fmul_rn(-2.0f, g));
                bool hit = act && (d2 < RADIUS2);
                unsigned m = __ballot_sync(FULLMASK, hit);
                int nh = __popc(m);
                cnt_nb += nh;
                int jj = hit ? (int)g_bidx[sb_ + s] : 0;
                if (nhit + nh <= HL_CAP) {
                    if (hit)
                        myhl[nhit + __popc(m & ((1u << lane) - 1u))] =
                            (unsigned short)jj;
                    nhit += nh;
                } else {
                    // overflow: process inline (pathological inputs only)
                    while (m) {
                        int l = __ffs(m) - 1; m &= m - 1;
                        int j = __shfl_sync(FULLMASK, jj, l);
                        float v = embb[j * DIM + lane];
                        float p = __fmul_rn(v, ei);
                        #pragma unroll
                        for (int o = 16; o; o >>= 1)
                            p += __shfl_xor_sync(FULLMASK, p, o);
                        float sim = __fdiv_rn(p, __fmul_rn(ni, normb[j]));
                        if (sim > SIM_T) { acc += v; cnt_sim++; }
                    }
                }
            }
        }
    }

    // ---- sort hit list ascending by original index (deterministic order) ----
    if (nhit <= 32) {
        int v = (lane < nhit) ? (int)myhl[lane] : 0x10000;
        #pragma unroll
        for (int k = 2; k <= 32; k <<= 1) {
            #pragma unroll
            for (int j = k >> 1; j > 0; j >>= 1) {
                int o = __shfl_xor_sync(FULLMASK, v, j);
                bool up    = ((lane & k) == 0);
                bool lower = ((lane & j) == 0);
                v = (up == lower) ? min(v, o) : max(v, o);
            }
        }
        if (lane < nhit) myhl[lane] = (unsigned short)v;
    } else if (lane == 0) {                      // rare path
        for (int a = 1; a < nhit; a++) {
            unsigned short key = myhl[a];
            int c = a - 1;
            while (c >= 0 && myhl[c] > key) { myhl[c + 1] = myhl[c]; c--; }
            myhl[c + 1] = key;
        }
    }
    __syncwarp();

    // ---- Phase B: 4-way interleaved similarity reductions ----
    for (int t = 0; t < nhit; t += 4) {
        int r = nhit - t;
        int j0 = myhl[t];
        int j1 = myhl[t + ((r > 1) ? 1 : 0)];
        int j2 = myhl[t + ((r > 2) ? 2 : 0)];
        int j3 = myhl[t + ((r > 3) ? 3 : 0)];

        float v0 = embb[j0 * DIM + lane];
        float v1 = embb[j1 * DIM + lane];
        float v2 = embb[j2 * DIM + lane];
        float v3 = embb[j3 * DIM + lane];
        float n0 = normb[j0], n1 = normb[j1], n2 = normb[j2], n3 = normb[j3];

        float p0 = __fmul_rn(v0, ei);
        float p1 = __fmul_rn(v1, ei);
        float p2 = __fmul_rn(v2, ei);
        float p3 = __fmul_rn(v3, ei);
        #pragma unroll
        for (int o = 16; o; o >>= 1) {
            p0 += __shfl_xor_sync(FULLMASK, p0, o);
            p1 += __shfl_xor_sync(FULLMASK, p1, o);
            p2 += __shfl_xor_sync(FULLMASK, p2, o);
            p3 += __shfl_xor_sync(FULLMASK, p3, o);
        }
        float s0 = __fdiv_rn(p0, __fmul_rn(ni, n0));
        float s1 = __fdiv_rn(p1, __fmul_rn(ni, n1));
        float s2 = __fdiv_rn(p2, __fmul_rn(ni, n2));
        float s3 = __fdiv_rn(p3, __fmul_rn(ni, n3));

        if (s0 > SIM_T)          { acc += v0; cnt_sim++; }
        if (r > 1 && s1 > SIM_T) { acc += v1; cnt_sim++; }
        if (r > 2 && s2 > SIM_T) { acc += v2; cnt_sim++; }
        if (r > 3 && s3 > SIM_T) { acc += v3; cnt_sim++; }
    }

    float mean = acc / (float)max(cnt_sim, 1);

    // ---- MLP: h = relu([emb_i, mean] @ W1 + b1); o = h @ W2 + b2 ----
    float h = sb1[lane];
    #pragma unroll
    for (int k = 0; k < 32; k++) {
        float ck = __shfl_sync(FULLMASK, ei, k);
        h = __fmaf_rn(ck, sW1[k * DIM + lane], h);
    }
    #pragma unroll
    for (int k = 0; k < 32; k++) {
        float ck = __shfl_sync(FULLMASK, mean, k);
        h = __fmaf_rn(ck, sW1[(k + 32) * DIM + lane], h);
    }
    h = fmaxf(h, 0.0f);

    float o = sb2[lane];
    #pragma unroll
    for (int k = 0; k < 32; k++) {
        float hk = __shfl_sync(FULLMASK, h, k);
        o = __fmaf_rn(hk, sW2[k * DIM + lane], o);
    }

    if (cnt_nb > 1 && cnt_sim > 0)
        out[gi * DIM + lane] = o;
}

// ---------------------------------------------------------------------------
extern "C" void kernel_launch(void* const* d_in, const int* in_sizes, int n_in,
                              void* d_out, int out_size)
{
    const float* points    = (const float*)d_in[0];
    const float* emb       = (const float*)d_in[1];
    const int*   leaf_mask = (const int*)  d_in[2];
    const float* W1        = (const float*)d_in[3];
    const float* b1        = (const float*)d_in[4];
    const float* W2        = (const float*)d_in[5];
    const float* b2        = (const float*)d_in[6];
    float* out = (float*)d_out;

    prep_kernel<<<(PREP_THR + 255) / 256, 256>>>(points, emb, leaf_mask, out);
    scan_kernel<<<BATCH, 1024>>>();
    scatter_kernel<<<(NP + 255) / 256, 256>>>();

    dim3 grid((NPTS + MWPB - 1) / MWPB, BATCH);
    main_kernel<<<grid, MT>>>(emb, W1, b1, W2, b2, out);
}